// round 1
// baseline (speedup 1.0000x reference)
#include <cuda_runtime.h>
#include <cstdint>

#define NNODES 50000
#define HID    128
#define NREL   9
#define NEDGES 600000
#define RNBUCK (NREL * NNODES)          // 450000 buckets

#define SCAN_CHUNK   2048
#define SCAN_NBLOCKS ((RNBUCK + SCAN_CHUNK - 1) / SCAN_CHUNK)   // 220

// ---------------- scratch (device globals; no allocation allowed) ----------
__device__ int g_counts[RNBUCK];
__device__ int g_offsets[RNBUCK + 1];
__device__ int g_cursor[RNBUCK];
__device__ int g_sorted_src[NEDGES];
__device__ int g_bsums[SCAN_NBLOCKS];
__device__ __align__(256) float g_H[2][(size_t)NNODES * HID];   // ping-pong hidden

// ---------------- helpers --------------------------------------------------
__device__ __forceinline__ float tf32r(float x) {
    uint32_t u;
    asm("cvt.rna.tf32.f32 %0, %1;" : "=r"(u) : "f"(x));
    return __uint_as_float(u);
}

__device__ __forceinline__ void mma_tf32(float& c0, float& c1, float& c2, float& c3,
                                         uint32_t a0, uint32_t a1, uint32_t a2, uint32_t a3,
                                         uint32_t b0, uint32_t b1) {
    asm volatile(
        "mma.sync.aligned.m16n8k8.row.col.f32.tf32.tf32.f32 "
        "{%0,%1,%2,%3}, {%4,%5,%6,%7}, {%8,%9}, {%0,%1,%2,%3};\n"
        : "+f"(c0), "+f"(c1), "+f"(c2), "+f"(c3)
        : "r"(a0), "r"(a1), "r"(a2), "r"(a3), "r"(b0), "r"(b1));
}

// ---------------- CSR build kernels ----------------------------------------
__global__ void k_zero_counts() {
    int i = blockIdx.x * blockDim.x + threadIdx.x;
    if (i < RNBUCK) g_counts[i] = 0;
}

__global__ void k_histogram(const int* __restrict__ dest, const int* __restrict__ etype) {
    int e = blockIdx.x * blockDim.x + threadIdx.x;
    if (e < NEDGES) {
        int key = etype[e] * NNODES + dest[e];
        atomicAdd(&g_counts[key], 1);
    }
}

__global__ void k_scanA() {   // per-chunk reduction -> g_bsums
    int base = blockIdx.x * SCAN_CHUNK;
    int sum = 0;
    for (int i = threadIdx.x; i < SCAN_CHUNK; i += blockDim.x) {
        int idx = base + i;
        if (idx < RNBUCK) sum += g_counts[idx];
    }
    for (int o = 16; o; o >>= 1) sum += __shfl_down_sync(0xffffffffu, sum, o);
    __shared__ int ws[8];
    if ((threadIdx.x & 31) == 0) ws[threadIdx.x >> 5] = sum;
    __syncthreads();
    if (threadIdx.x == 0) {
        int t = 0;
        #pragma unroll
        for (int w = 0; w < 8; w++) t += ws[w];
        g_bsums[blockIdx.x] = t;
    }
}

__global__ void k_scanB() {   // serial exclusive scan of 220 block sums
    if (threadIdx.x == 0) {
        int acc = 0;
        for (int i = 0; i < SCAN_NBLOCKS; i++) {
            int v = g_bsums[i];
            g_bsums[i] = acc;
            acc += v;
        }
        g_offsets[RNBUCK] = acc;   // = NEDGES
    }
}

__global__ void k_scanC() {   // full exclusive scan, write offsets + cursor
    __shared__ int warp_sums[8];
    int base = blockIdx.x * SCAN_CHUNK;
    int t = threadIdx.x, lane = t & 31, wid = t >> 5;
    int mybase = base + t * 8;
    int loc[8];
    int s = 0;
    #pragma unroll
    for (int j = 0; j < 8; j++) {
        int idx = mybase + j;
        int v = (idx < RNBUCK) ? g_counts[idx] : 0;
        loc[j] = s;
        s += v;
    }
    int x = s;
    for (int o = 1; o < 32; o <<= 1) {
        int y = __shfl_up_sync(0xffffffffu, x, o);
        if (lane >= o) x += y;
    }
    if (lane == 31) warp_sums[wid] = x;     // warp total (inclusive of last thread)
    __syncthreads();
    if (t == 0) {
        int acc = 0;
        #pragma unroll
        for (int w = 0; w < 8; w++) {
            int v = warp_sums[w];
            warp_sums[w] = acc;
            acc += v;
        }
    }
    __syncthreads();
    int thread_off = warp_sums[wid] + (x - s) + g_bsums[blockIdx.x];
    #pragma unroll
    for (int j = 0; j < 8; j++) {
        int idx = mybase + j;
        if (idx < RNBUCK) {
            int o = thread_off + loc[j];
            g_offsets[idx] = o;
            g_cursor[idx]  = o;
        }
    }
}

__global__ void k_scatter(const int* __restrict__ dest, const int* __restrict__ etype,
                          const int* __restrict__ src) {
    int e = blockIdx.x * blockDim.x + threadIdx.x;
    if (e < NEDGES) {
        int key = etype[e] * NNODES + dest[e];
        int pos = atomicAdd(&g_cursor[key], 1);
        g_sorted_src[pos] = src[e];
    }
}

// ---------------- fused layer kernel ---------------------------------------
// Block: 64 dest rows x 128 out cols. 256 threads = 8 warps, warp grid 4(M) x 2(N).
// Per relation r: gather-sum H[src] rows into smem A (tf32-rounded), load W[l,r]
// into smem (tf32-rounded), accumulate C += A @ W with mma.sync tf32.
// Epilogue: += sum_r cnt[r,row]*b[l,r,col], optional relu.
#define MT 64
#define APAD 132          // 128 + 4 float padding
#define SMEM_FLOATS (MT * APAD + HID * APAD + NREL * HID)
#define SMEM_BYTES  (SMEM_FLOATS * 4 + NREL * MT * 4)

__global__ void __launch_bounds__(256)
k_rgcn_layer(const float* __restrict__ Hin, const float* __restrict__ W,
             const float* __restrict__ Bv, float* __restrict__ Hout, int relu) {
    extern __shared__ float smem[];
    float* A_s  = smem;                       // [MT][APAD]
    float* W_s  = A_s + MT * APAD;            // [HID][APAD]
    float* b_s  = W_s + HID * APAD;           // [NREL][HID]
    int*   cnt_s = (int*)(b_s + NREL * HID);  // [NREL][MT]

    const int tid = threadIdx.x;
    const int lane = tid & 31;
    const int wid  = tid >> 5;
    const int base = blockIdx.x * MT;

    // per-tile constants: counts and biases
    for (int i = tid; i < NREL * MT; i += 256) {
        int r = i / MT, m = i % MT;
        int d = base + m;
        cnt_s[i] = (d < NNODES)
                 ? (g_offsets[r * NNODES + d + 1] - g_offsets[r * NNODES + d]) : 0;
    }
    for (int i = tid; i < NREL * HID; i += 256) b_s[i] = Bv[i];

    const int wm = wid & 3;          // row group: rows [wm*16, wm*16+16)
    const int wn = wid >> 2;         // col group: cols [wn*64, wn*64+64)
    const int g  = lane >> 2;        // 0..7
    const int tg = lane & 3;         // 0..3

    float c[8][4];
    #pragma unroll
    for (int nt = 0; nt < 8; nt++)
        #pragma unroll
        for (int j = 0; j < 4; j++) c[nt][j] = 0.0f;

    for (int r = 0; r < NREL; r++) {
        __syncthreads();   // protect smem reuse (and covers the const loads at r=0)

        // ---- gather: warp w builds rows [w*8, w*8+8) of A_s ----
        #pragma unroll
        for (int mr = 0; mr < 8; mr++) {
            int m = wid * 8 + mr;
            int d = base + m;
            float4 acc0 = make_float4(0.f, 0.f, 0.f, 0.f);
            float4 acc1 = make_float4(0.f, 0.f, 0.f, 0.f);
            if (d < NNODES) {
                int e0 = g_offsets[r * NNODES + d];
                int e1 = g_offsets[r * NNODES + d + 1];
                int e = e0;
                // 2-way ILP on the accumulation chain
                for (; e + 1 < e1; e += 2) {
                    int s0 = g_sorted_src[e];
                    int s1 = g_sorted_src[e + 1];
                    float4 v0 = *(const float4*)(Hin + (size_t)s0 * HID + lane * 4);
                    float4 v1 = *(const float4*)(Hin + (size_t)s1 * HID + lane * 4);
                    acc0.x += v0.x; acc0.y += v0.y; acc0.z += v0.z; acc0.w += v0.w;
                    acc1.x += v1.x; acc1.y += v1.y; acc1.z += v1.z; acc1.w += v1.w;
                }
                if (e < e1) {
                    int s0 = g_sorted_src[e];
                    float4 v0 = *(const float4*)(Hin + (size_t)s0 * HID + lane * 4);
                    acc0.x += v0.x; acc0.y += v0.y; acc0.z += v0.z; acc0.w += v0.w;
                }
            }
            float4 out;
            out.x = tf32r(acc0.x + acc1.x);
            out.y = tf32r(acc0.y + acc1.y);
            out.z = tf32r(acc0.z + acc1.z);
            out.w = tf32r(acc0.w + acc1.w);
            *(float4*)(A_s + m * APAD + lane * 4) = out;
        }

        // ---- load W[l,r] (128x128) to smem, tf32-rounded ----
        const float4* Wg = (const float4*)(W + (size_t)r * HID * HID);
        for (int i = tid; i < HID * HID / 4; i += 256) {
            float4 v = Wg[i];
            v.x = tf32r(v.x); v.y = tf32r(v.y); v.z = tf32r(v.z); v.w = tf32r(v.w);
            int idx = i * 4;
            int row = idx >> 7, col = idx & 127;
            *(float4*)(W_s + row * APAD + col) = v;
        }
        __syncthreads();

        // ---- MMA: C += A(64x128) @ W(128x128), warp tile 16x64 ----
        #pragma unroll 4
        for (int kk = 0; kk < HID; kk += 8) {
            const int ar0 = (wm * 16 + g) * APAD;
            const int ar1 = (wm * 16 + g + 8) * APAD;
            uint32_t a0 = __float_as_uint(A_s[ar0 + kk + tg]);
            uint32_t a1 = __float_as_uint(A_s[ar1 + kk + tg]);
            uint32_t a2 = __float_as_uint(A_s[ar0 + kk + tg + 4]);
            uint32_t a3 = __float_as_uint(A_s[ar1 + kk + tg + 4]);
            #pragma unroll
            for (int nt = 0; nt < 8; nt++) {
                int ncol = wn * 64 + nt * 8 + g;
                uint32_t b0 = __float_as_uint(W_s[(kk + tg) * APAD + ncol]);
                uint32_t b1 = __float_as_uint(W_s[(kk + tg + 4) * APAD + ncol]);
                mma_tf32(c[nt][0], c[nt][1], c[nt][2], c[nt][3],
                         a0, a1, a2, a3, b0, b1);
            }
        }
    }

    // ---- epilogue: bias via counts, relu, store ----
    const int m0 = wm * 16 + g;
    const int m1 = m0 + 8;
    const int d0 = base + m0;
    const int d1 = base + m1;
    #pragma unroll
    for (int nt = 0; nt < 8; nt++) {
        int col0 = wn * 64 + nt * 8 + tg * 2;
        float v00 = c[nt][0], v01 = c[nt][1], v10 = c[nt][2], v11 = c[nt][3];
        #pragma unroll
        for (int r = 0; r < NREL; r++) {
            float c0 = (float)cnt_s[r * MT + m0];
            float c1 = (float)cnt_s[r * MT + m1];
            float bb0 = b_s[r * HID + col0];
            float bb1 = b_s[r * HID + col0 + 1];
            v00 += c0 * bb0; v01 += c0 * bb1;
            v10 += c1 * bb0; v11 += c1 * bb1;
        }
        if (relu) {
            v00 = fmaxf(v00, 0.f); v01 = fmaxf(v01, 0.f);
            v10 = fmaxf(v10, 0.f); v11 = fmaxf(v11, 0.f);
        }
        if (d0 < NNODES) {
            Hout[(size_t)d0 * HID + col0]     = v00;
            Hout[(size_t)d0 * HID + col0 + 1] = v01;
        }
        if (d1 < NNODES) {
            Hout[(size_t)d1 * HID + col0]     = v10;
            Hout[(size_t)d1 * HID + col0 + 1] = v11;
        }
    }
}

// ---------------- launch ----------------------------------------------------
extern "C" void kernel_launch(void* const* d_in, const int* in_sizes, int n_in,
                              void* d_out, int out_size) {
    const int*   eidx  = (const int*)d_in[0];      // [2, NEDGES]: row0=dest, row1=src
    const int*   etype = (const int*)d_in[1];      // [NEDGES]
    const float* emb   = (const float*)d_in[2];    // [NNODES, HID]
    const float* wts   = (const float*)d_in[3];    // [3, NREL, HID, HID]
    const float* bias  = (const float*)d_in[4];    // [3, NREL, HID]
    float*       out   = (float*)d_out;            // [NNODES, HID]

    const int* dest = eidx;
    const int* src  = eidx + NEDGES;

    float* hbuf = nullptr;
    cudaGetSymbolAddress((void**)&hbuf, g_H);
    float* H0 = hbuf;
    float* H1 = hbuf + (size_t)NNODES * HID;

    // CSR build (per call; edge data could differ between calls in principle)
    k_zero_counts<<<(RNBUCK + 1023) / 1024, 1024>>>();
    k_histogram<<<(NEDGES + 255) / 256, 256>>>(dest, etype);
    k_scanA<<<SCAN_NBLOCKS, 256>>>();
    k_scanB<<<1, 32>>>();
    k_scanC<<<SCAN_NBLOCKS, 256>>>();
    k_scatter<<<(NEDGES + 255) / 256, 256>>>(dest, etype, src);

    static_assert(SMEM_BYTES < 228 * 1024, "smem too big");
    cudaFuncSetAttribute(k_rgcn_layer, cudaFuncAttributeMaxDynamicSharedMemorySize,
                         SMEM_BYTES);

    const int grid = (NNODES + MT - 1) / MT;   // 782
    const size_t wstride = (size_t)NREL * HID * HID;
    const size_t bstride = (size_t)NREL * HID;

    k_rgcn_layer<<<grid, 256, SMEM_BYTES>>>(emb, wts,               bias,               H0,  1);
    k_rgcn_layer<<<grid, 256, SMEM_BYTES>>>(H0,  wts + wstride,     bias + bstride,     H1,  1);
    k_rgcn_layer<<<grid, 256, SMEM_BYTES>>>(H1,  wts + 2 * wstride, bias + 2 * bstride, out, 0);
}

// round 6
// speedup vs baseline: 1.0923x; 1.0923x over previous
#include <cuda_runtime.h>
#include <cstdint>

#define NNODES 50000
#define HID    128
#define NREL   9
#define NEDGES 600000
#define RNBUCK (NREL * NNODES)

#define SCAN_CHUNK   2048
#define SCAN_NBLOCKS ((RNBUCK + SCAN_CHUNK - 1) / SCAN_CHUNK)   // 220

#define MT      128                         // M rows per block tile
#define GRID_L  ((NNODES + MT - 1) / MT)    // 391
#define THREADS 512                         // 8 producer + 8 consumer warps
#define APAD    132

// ---------------- scratch (device globals; no allocation allowed) ----------
__device__ int g_counts[RNBUCK];
__device__ int g_offsets[RNBUCK + 1];
__device__ int g_cursor[RNBUCK];
__device__ int g_sorted_src[NEDGES];
__device__ int g_bsums[SCAN_NBLOCKS];
__device__ __align__(256) float g_H[2][(size_t)NNODES * HID];
__device__ __align__(256) float g_Wt[3 * NREL * HID * HID];   // tf32-pre-rounded W

// ---------------- helpers --------------------------------------------------
__device__ __forceinline__ float tf32r(float x) {
    uint32_t u;
    asm("cvt.rna.tf32.f32 %0, %1;" : "=r"(u) : "f"(x));
    return __uint_as_float(u);
}
__device__ __forceinline__ void mma_tf32(float& c0, float& c1, float& c2, float& c3,
                                         uint32_t a0, uint32_t a1, uint32_t a2, uint32_t a3,
                                         uint32_t b0, uint32_t b1) {
    asm volatile(
        "mma.sync.aligned.m16n8k8.row.col.f32.tf32.tf32.f32 "
        "{%0,%1,%2,%3}, {%4,%5,%6,%7}, {%8,%9}, {%0,%1,%2,%3};\n"
        : "+f"(c0), "+f"(c1), "+f"(c2), "+f"(c3)
        : "r"(a0), "r"(a1), "r"(a2), "r"(a3), "r"(b0), "r"(b1));
}
__device__ __forceinline__ void bar_sync(int id, int cnt) {
    asm volatile("bar.sync %0, %1;" :: "r"(id), "r"(cnt) : "memory");
}
__device__ __forceinline__ void bar_arrive(int id, int cnt) {
    asm volatile("bar.arrive %0, %1;" :: "r"(id), "r"(cnt) : "memory");
}

// ---------------- CSR build ----------------
__global__ void k_zero_counts() {
    int i = blockIdx.x * blockDim.x + threadIdx.x;
    if (i < RNBUCK) g_counts[i] = 0;
}
__global__ void k_histogram(const int* __restrict__ dest, const int* __restrict__ etype) {
    int e = blockIdx.x * blockDim.x + threadIdx.x;
    if (e < NEDGES) atomicAdd(&g_counts[etype[e] * NNODES + dest[e]], 1);
}
__global__ void k_scanA() {
    int base = blockIdx.x * SCAN_CHUNK;
    int sum = 0;
    for (int i = threadIdx.x; i < SCAN_CHUNK; i += blockDim.x) {
        int idx = base + i;
        if (idx < RNBUCK) sum += g_counts[idx];
    }
    for (int o = 16; o; o >>= 1) sum += __shfl_down_sync(0xffffffffu, sum, o);
    __shared__ int ws[8];
    if ((threadIdx.x & 31) == 0) ws[threadIdx.x >> 5] = sum;
    __syncthreads();
    if (threadIdx.x == 0) {
        int t = 0;
        #pragma unroll
        for (int w = 0; w < 8; w++) t += ws[w];
        g_bsums[blockIdx.x] = t;
    }
}
__global__ void k_scanB() {   // parallel exclusive scan of 220 block sums (256 thr)
    int t = threadIdx.x, lane = t & 31, w = t >> 5;
    int v = (t < SCAN_NBLOCKS) ? g_bsums[t] : 0;
    int x = v;
    for (int o = 1; o < 32; o <<= 1) {
        int y = __shfl_up_sync(0xffffffffu, x, o);
        if (lane >= o) x += y;
    }
    __shared__ int ws[8];
    if (lane == 31) ws[w] = x;
    __syncthreads();
    if (t == 0) {
        int acc = 0;
        #pragma unroll
        for (int i = 0; i < 8; i++) { int tv = ws[i]; ws[i] = acc; acc += tv; }
    }
    __syncthreads();
    int incl = x + ws[w];
    if (t < SCAN_NBLOCKS) g_bsums[t] = incl - v;
    if (t == SCAN_NBLOCKS - 1) g_offsets[RNBUCK] = incl;
}
__global__ void k_scanC() {
    __shared__ int warp_sums[8];
    int base = blockIdx.x * SCAN_CHUNK;
    int t = threadIdx.x, lane = t & 31, wid = t >> 5;
    int mybase = base + t * 8;
    int loc[8];
    int s = 0;
    #pragma unroll
    for (int j = 0; j < 8; j++) {
        int idx = mybase + j;
        int v = (idx < RNBUCK) ? g_counts[idx] : 0;
        loc[j] = s; s += v;
    }
    int x = s;
    for (int o = 1; o < 32; o <<= 1) {
        int y = __shfl_up_sync(0xffffffffu, x, o);
        if (lane >= o) x += y;
    }
    if (lane == 31) warp_sums[wid] = x;
    __syncthreads();
    if (t == 0) {
        int acc = 0;
        #pragma unroll
        for (int w = 0; w < 8; w++) { int v = warp_sums[w]; warp_sums[w] = acc; acc += v; }
    }
    __syncthreads();
    int off = warp_sums[wid] + (x - s) + g_bsums[blockIdx.x];
    #pragma unroll
    for (int j = 0; j < 8; j++) {
        int idx = mybase + j;
        if (idx < RNBUCK) { int o = off + loc[j]; g_offsets[idx] = o; g_cursor[idx] = o; }
    }
}
__global__ void k_scatter(const int* __restrict__ dest, const int* __restrict__ etype,
                          const int* __restrict__ src) {
    int e = blockIdx.x * blockDim.x + threadIdx.x;
    if (e < NEDGES) {
        int pos = atomicAdd(&g_cursor[etype[e] * NNODES + dest[e]], 1);
        g_sorted_src[pos] = src[e];
    }
}

// ---------------- W prep: tf32-round all 27 weight matrices -----------------
__global__ void k_prepW(const float* __restrict__ W) {
    size_t i = (size_t)blockIdx.x * blockDim.x + threadIdx.x;
    if (i < (size_t)3 * NREL * HID * HID) g_Wt[i] = tf32r(W[i]);
}

// ---------------- fused layer kernel: warp-specialized ----------------------
// 512 threads. Warps 0-7 = producers: gather-sum H[src] rows of relation r into
// double-buffered smem A[b] (tf32-rounded). Warps 8-15 = consumers: per
// relation load W[l,r] into smem, then C += A[b] @ W with mma.sync tf32.
// Named barriers: full[b]=3+b (prod arrive / cons sync), empty[b]=1+b
// (cons arrive / prod sync), 5 = consumer-only (W buffer reuse + visibility).
struct SMem {
    float A[2][MT * APAD];       // 2 x 67.6 KB
    float W[HID * APAD];         // 67.6 KB
    float bias[NREL * HID];      // 4.5 KB
};

__global__ void __launch_bounds__(THREADS, 1)
k_layer(const float* __restrict__ Hin, const float* __restrict__ Wt_l,
        const float* __restrict__ Bv, float* __restrict__ Hout, int relu) {
    extern __shared__ __align__(16) char smraw[];
    SMem* sm = (SMem*)smraw;

    const int tid  = threadIdx.x;
    const int lane = tid & 31;
    const int wid  = tid >> 5;
    const int base = blockIdx.x * MT;

    for (int i = tid; i < NREL * HID; i += THREADS) sm->bias[i] = Bv[i];
    __syncthreads();

    if (wid < 8) {
        // ================= PRODUCER =================
        const int rowbase = wid * 16;              // 16 rows per warp
        const int mycol   = lane * 4;

        for (int r = 0; r < NREL; r++) {
            const int b = r & 1;
            if (r >= 2) bar_sync(1 + b, 512);      // wait A[b] empty
            float* Ab = sm->A[b];

            const int d0 = base + rowbase;
            int dd = d0 + lane;
            if (dd > NNODES) dd = NNODES;
            int offl = 0;
            if (lane <= 16) offl = g_offsets[r * NNODES + dd];
            const int e0  = __shfl_sync(0xffffffffu, offl, 0);
            const int eE  = __shfl_sync(0xffffffffu, offl, 16);
            const int cnt = eE - e0;

            float4 acc = make_float4(0.f, 0.f, 0.f, 0.f);
            int cur = 0;
            int nextb = __shfl_sync(0xffffffffu, offl, 1) - e0;

            #define FLUSH() do { \
                float4 o; o.x = tf32r(acc.x); o.y = tf32r(acc.y); \
                o.z = tf32r(acc.z); o.w = tf32r(acc.w); \
                *(float4*)(Ab + (rowbase + cur) * APAD + mycol) = o; \
                acc.x = acc.y = acc.z = acc.w = 0.f; \
                cur++; \
                int nb2 = __shfl_sync(0xffffffffu, offl, (cur < 16) ? (cur + 1) : 16); \
                nextb = (cur < 16) ? (nb2 - e0) : 0x7fffffff; \
            } while (0)

            for (int ib = 0; ib < cnt; ib += 32) {
                int rem = cnt - ib; if (rem > 32) rem = 32;
                int sv = 0;
                if (lane < rem) sv = g_sorted_src[e0 + ib + lane];
                int j = 0;
                while (j < rem) {
                    int nb = rem - j; if (nb > 8) nb = 8;
                    float4 v[8];
                    #pragma unroll
                    for (int u = 0; u < 8; u++) {
                        if (u < nb) {
                            int s = __shfl_sync(0xffffffffu, sv, j + u);
                            v[u] = *(const float4*)(Hin + (size_t)s * HID + mycol);
                        }
                    }
                    #pragma unroll
                    for (int u = 0; u < 8; u++) {
                        if (u < nb) {
                            int idx = ib + j + u;
                            while (idx >= nextb) FLUSH();
                            acc.x += v[u].x; acc.y += v[u].y;
                            acc.z += v[u].z; acc.w += v[u].w;
                        }
                    }
                    j += nb;
                }
            }
            while (cur < 16) FLUSH();
            #undef FLUSH

            bar_arrive(3 + b, 512);                // signal A[b] full
        }
    } else {
        // ================= CONSUMER =================
        const int cw = wid - 8;
        const int wm = cw & 3;                     // M group: rows [wm*32, +32)
        const int wn = cw >> 1 & 0;                // placeholder (see below)
        const int wncol = (cw >> 2) * 64;          // N group: cols [wncol, +64)
        const int g  = lane >> 2;
        const int tg = lane & 3;
        const int ctid = tid - 256;                // 0..255

        float c[2][8][4];
        #pragma unroll
        for (int m2 = 0; m2 < 2; m2++)
            #pragma unroll
            for (int nt = 0; nt < 8; nt++)
                #pragma unroll
                for (int j = 0; j < 4; j++) c[m2][nt][j] = 0.0f;

        for (int r = 0; r < NREL; r++) {
            const int b = r & 1;

            if (r > 0) bar_sync(5, 256);           // all consumers done with W
            {   // load pre-rounded W[l,r] into smem
                const float4* src = (const float4*)(Wt_l + (size_t)r * (HID * HID));
                #pragma unroll
                for (int i = ctid; i < (HID * HID) / 4; i += 256) {
                    float4 v = src[i];
                    int idx = i * 4;
                    *(float4*)(sm->W + (idx >> 7) * APAD + (idx & 127)) = v;
                }
            }
            bar_sync(5, 256);                      // W visible to all consumers
            bar_sync(3 + b, 512);                  // wait A[b] full

            const float* Ab = sm->A[b];
            #pragma unroll 4
            for (int kk = 0; kk < HID; kk += 8) {
                const int a00 = (wm * 32 + g) * APAD + kk + tg;
                const int a10 = (wm * 32 + 16 + g) * APAD + kk + tg;
                uint32_t a0[2], a1[2], a2[2], a3[2];
                a0[0] = __float_as_uint(Ab[a00]);
                a1[0] = __float_as_uint(Ab[a00 + 8 * APAD]);
                a2[0] = __float_as_uint(Ab[a00 + 4]);
                a3[0] = __float_as_uint(Ab[a00 + 8 * APAD + 4]);
                a0[1] = __float_as_uint(Ab[a10]);
                a1[1] = __float_as_uint(Ab[a10 + 8 * APAD]);
                a2[1] = __float_as_uint(Ab[a10 + 4]);
                a3[1] = __float_as_uint(Ab[a10 + 8 * APAD + 4]);
                #pragma unroll
                for (int nt = 0; nt < 8; nt++) {
                    const int ncol = wncol + nt * 8 + g;
                    uint32_t b0 = __float_as_uint(sm->W[(kk + tg) * APAD + ncol]);
                    uint32_t b1 = __float_as_uint(sm->W[(kk + tg + 4) * APAD + ncol]);
                    mma_tf32(c[0][nt][0], c[0][nt][1], c[0][nt][2], c[0][nt][3],
                             a0[0], a1[0], a2[0], a3[0], b0, b1);
                    mma_tf32(c[1][nt][0], c[1][nt][1], c[1][nt][2], c[1][nt][3],
                             a0[1], a1[1], a2[1], a3[1], b0, b1);
                }
            }
            bar_arrive(1 + b, 512);                // signal A[b] empty
        }

        // ---- epilogue: bias via per-row counts, relu, store ----
        (void)wn;
        #pragma unroll
        for (int m2 = 0; m2 < 2; m2++) {
            #pragma unroll
            for (int h = 0; h < 2; h++) {
                const int row = wm * 32 + m2 * 16 + h * 8 + g;
                const int d = base + row;
                if (d >= NNODES) continue;
                float cnt[NREL];
                #pragma unroll
                for (int r = 0; r < NREL; r++)
                    cnt[r] = (float)(g_offsets[r * NNODES + d + 1]
                                   - g_offsets[r * NNODES + d]);
                #pragma unroll
                for (int nt = 0; nt < 8; nt++) {
                    const int col0 = wncol + nt * 8 + tg * 2;
                    float v0 = c[m2][nt][h * 2 + 0];
                    float v1 = c[m2][nt][h * 2 + 1];
                    #pragma unroll
                    for (int r = 0; r < NREL; r++) {
                        const float cc = cnt[r];
                        v0 += cc * sm->bias[r * HID + col0];
                        v1 += cc * sm->bias[r * HID + col0 + 1];
                    }
                    if (relu) { v0 = fmaxf(v0, 0.f); v1 = fmaxf(v1, 0.f); }
                    Hout[(size_t)d * HID + col0]     = v0;
                    Hout[(size_t)d * HID + col0 + 1] = v1;
                }
            }
        }
    }
}

// ---------------- launch ----------------------------------------------------
extern "C" void kernel_launch(void* const* d_in, const int* in_sizes, int n_in,
                              void* d_out, int out_size) {
    const int*   eidx  = (const int*)d_in[0];      // [2, NEDGES]: row0=dest, row1=src
    const int*   etype = (const int*)d_in[1];
    const float* emb   = (const float*)d_in[2];
    const float* wts   = (const float*)d_in[3];    // [3, NREL, HID, HID]
    const float* bias  = (const float*)d_in[4];    // [3, NREL, HID]
    float*       out   = (float*)d_out;

    const int* dest = eidx;
    const int* src  = eidx + NEDGES;

    float* hbuf = nullptr;
    cudaGetSymbolAddress((void**)&hbuf, g_H);
    float* H0 = hbuf;
    float* H1 = hbuf + (size_t)NNODES * HID;
    float* wt = nullptr;
    cudaGetSymbolAddress((void**)&wt, g_Wt);

    // CSR build
    k_zero_counts<<<(RNBUCK + 1023) / 1024, 1024>>>();
    k_histogram<<<(NEDGES + 255) / 256, 256>>>(dest, etype);
    k_scanA<<<SCAN_NBLOCKS, 256>>>();
    k_scanB<<<1, 256>>>();
    k_scanC<<<SCAN_NBLOCKS, 256>>>();
    k_scatter<<<(NEDGES + 255) / 256, 256>>>(dest, etype, src);

    // W prep (tf32 rounding, once)
    {
        const int tot = 3 * NREL * HID * HID;
        k_prepW<<<(tot + 255) / 256, 256>>>(wts);
    }

    const int smem_sz = (int)sizeof(SMem);
    static_assert(sizeof(SMem) <= 227 * 1024, "smem too big");
    cudaFuncSetAttribute(k_layer, cudaFuncAttributeMaxDynamicSharedMemorySize, smem_sz);

    const size_t wstride = (size_t)NREL * HID * HID;
    const size_t bstride = (size_t)NREL * HID;

    k_layer<<<GRID_L, THREADS, smem_sz>>>(emb, wt,               bias,               H0,  1);
    k_layer<<<GRID_L, THREADS, smem_sz>>>(H0,  wt + wstride,     bias + bstride,     H1,  1);
    k_layer<<<GRID_L, THREADS, smem_sz>>>(H1,  wt + 2 * wstride, bias + 2 * bstride, out, 0);
}